// round 1
// baseline (speedup 1.0000x reference)
#include <cuda_runtime.h>

// Problem constants
#define B_   512
#define T_   100
#define L_   256
#define D_   128
#define NPT  511          // nodes per tree = 2*L-1
#define TL_  25600        // T * L
#define BT_  51200        // B * T

// ---------------------------------------------------------------------------
// Scratch (device globals: no allocation allowed)
// ---------------------------------------------------------------------------
__device__ float g_H[2][(size_t)TL_ * D_];   // ping-pong hidden state per level
__device__ float g_C[2][(size_t)TL_ * D_];   // ping-pong cell state per level
__device__ float g_Wt[256 * 512];            // W^T: [k=0..255][n=0..511], k = [x|h] dim
__device__ float g_bias[512];                // b_ih + b_hh
__device__ int   g_leaf[BT_];                // leaf index per (b,t), -1 if inactive

// ---------------------------------------------------------------------------
// Helpers
// ---------------------------------------------------------------------------
__device__ __forceinline__ void ffma2(unsigned long long &acc,
                                      unsigned long long a, unsigned long long b) {
    asm("fma.rn.f32x2 %0, %1, %2, %0;" : "+l"(acc) : "l"(a), "l"(b));
}
__device__ __forceinline__ unsigned long long dup2(float z) {
    unsigned long long r;
    asm("mov.b64 %0, {%1, %1};" : "=l"(r) : "f"(z));
    return r;
}
__device__ __forceinline__ float2 unpk(unsigned long long v) {
    float2 r;
    asm("mov.b64 {%0, %1}, %2;" : "=f"(r.x), "=f"(r.y) : "l"(v));
    return r;
}
__device__ __forceinline__ float sigf(float x) {
    return __fdividef(1.f, 1.f + __expf(-x));
}
__device__ __forceinline__ float tanhf_(float x) {
    float e = __expf(2.f * x);               // saturates cleanly: e=0 -> -1, e=inf -> 1
    return 1.f - __fdividef(2.f, e + 1.f);
}

// ---------------------------------------------------------------------------
// Prep: transpose/concat weights to Wt[k][n], fuse biases
// ---------------------------------------------------------------------------
__global__ void prep_kernel(const float* __restrict__ w_ih, const float* __restrict__ w_hh,
                            const float* __restrict__ b_ih, const float* __restrict__ b_hh) {
    int idx = blockIdx.x * blockDim.x + threadIdx.x;
    if (idx < 256 * 512) {
        int d = idx >> 9;
        int n = idx & 511;
        g_Wt[idx] = (d < 128) ? w_ih[n * 128 + d] : w_hh[n * 128 + (d - 128)];
    }
    if (idx < 512) g_bias[idx] = b_ih[idx] + b_hh[idx];
}

// ---------------------------------------------------------------------------
// Argmax over the one-hot cross row: one warp per (b,t)
// ---------------------------------------------------------------------------
__global__ void leaf_kernel(const float* __restrict__ cross) {
    int gw   = (blockIdx.x * blockDim.x + threadIdx.x) >> 5;
    int lane = threadIdx.x & 31;
    if (gw >= BT_) return;
    const float* row = cross + (size_t)gw * L_;   // (b*T+t)*L contiguous
    float best = row[lane];
    int   bi   = lane;
    #pragma unroll
    for (int i = lane + 32; i < L_; i += 32) {
        float v = row[i];
        if (v > best) { best = v; bi = i; }
    }
    #pragma unroll
    for (int off = 16; off; off >>= 1) {
        float ob = __shfl_down_sync(0xffffffffu, best, off);
        int   oi = __shfl_down_sync(0xffffffffu, bi,   off);
        if (ob > best || (ob == best && oi < bi)) { best = ob; bi = oi; }
    }
    if (lane == 0) g_leaf[gw] = (best > 0.f) ? bi : -1;
}

// ---------------------------------------------------------------------------
// One LSTM tree level: rows m in [0, M=T<<level). t = m>>level, j = m&mask.
//   x   = node_emb[t*511 + (2^level - 1) + j]        (D=128)
//   h,c = state of parent row (m>>1) from previous level (0 at level 0)
//   g[512] = [x|h] @ Wt + bias ; standard LSTM cell -> H/C at this level.
// GEMM: M x 512 x 256, fp32 with packed f32x2 FMA. Thread owns 2 columns in
// EACH gate quadrant -> elementwise cell update is thread-local.
// ---------------------------------------------------------------------------
template<int TM, int THREADS, int ZSTRIDE>
__global__ void __launch_bounds__(THREADS, 1)
lstm_level_kernel(int level, int M, int first, int dst, const float* __restrict__ emb) {
    constexpr int KC = 16;
    constexpr int RG = THREADS / 64;   // row groups (64 column-groups fixed)
    constexpr int RM = TM / RG;        // rows per thread

    extern __shared__ float smem[];
    float* Zs = smem;                  // [256][ZSTRIDE] transposed input tile
    float* Ws = smem + 256 * ZSTRIDE;  // [KC][512] weight chunk

    const float* __restrict__ Hin  = g_H[dst ^ 1];
    const float* __restrict__ Cin  = g_C[dst ^ 1];
    float* __restrict__       Hout = g_H[dst];
    float* __restrict__       Cout = g_C[dst];

    const int tid = threadIdx.x;
    const int tx  = tid & 63;          // column group: owns cols {2tx, 2tx+1} per quadrant
    const int ty  = tid >> 6;          // row group
    const int m0  = blockIdx.x * TM;
    const int lmask = (1 << level) - 1;

    // Load Z tile (transposed): Zs[d][m] = [x | h_parent]
    for (int idx = tid; idx < TM * 256; idx += THREADS) {
        int m  = idx >> 8;
        int d  = idx & 255;
        int gm = m0 + m;
        float v = 0.f;
        if (gm < M) {
            if (d < 128) {
                int t = gm >> level;
                int j = gm & lmask;
                v = emb[((size_t)(t * NPT + lmask + j)) * D_ + d];
            } else if (!first) {
                v = Hin[((size_t)(gm >> 1)) * D_ + (d - 128)];
            }
        }
        Zs[d * ZSTRIDE + m] = v;
    }

    unsigned long long acc[RM][4];
    #pragma unroll
    for (int r = 0; r < RM; r++)
        #pragma unroll
        for (int q = 0; q < 4; q++) acc[r][q] = 0ull;

    __syncthreads();

    for (int kc = 0; kc < 256; kc += KC) {
        // Stage W chunk (KC x 512) into smem, cooperative float4 copy
        const float4* src  = (const float4*)(g_Wt + kc * 512);
        float4*       dstw = (float4*)Ws;
        #pragma unroll
        for (int i = 0; i < (KC * 512 / 4) / THREADS; i++)
            dstw[tid + i * THREADS] = src[tid + i * THREADS];
        __syncthreads();

        #pragma unroll
        for (int kk = 0; kk < KC; kk++) {
            const float* zrow = Zs + (kc + kk) * ZSTRIDE + ty * RM;
            unsigned long long a[RM];
            #pragma unroll
            for (int r = 0; r < RM; r++) a[r] = dup2(zrow[r]);
            const float* wrow = Ws + kk * 512 + tx * 2;
            unsigned long long b0 = *(const unsigned long long*)(wrow);
            unsigned long long b1 = *(const unsigned long long*)(wrow + 128);
            unsigned long long b2 = *(const unsigned long long*)(wrow + 256);
            unsigned long long b3 = *(const unsigned long long*)(wrow + 384);
            #pragma unroll
            for (int r = 0; r < RM; r++) {
                ffma2(acc[r][0], a[r], b0);
                ffma2(acc[r][1], a[r], b1);
                ffma2(acc[r][2], a[r], b2);
                ffma2(acc[r][3], a[r], b3);
            }
        }
        __syncthreads();
    }

    // Epilogue: bias + LSTM cell (thread-local: owns cols c0,c0+1 of each gate)
    const int c0 = tx * 2;
    const float bi0 = g_bias[c0],       bi1 = g_bias[c0 + 1];
    const float bf0 = g_bias[128 + c0], bf1 = g_bias[128 + c0 + 1];
    const float bg0 = g_bias[256 + c0], bg1 = g_bias[256 + c0 + 1];
    const float bo0 = g_bias[384 + c0], bo1 = g_bias[384 + c0 + 1];

    #pragma unroll
    for (int r = 0; r < RM; r++) {
        int gm = m0 + ty * RM + r;
        if (gm >= M) break;
        float2 gi = unpk(acc[r][0]);
        float2 gf = unpk(acc[r][1]);
        float2 gg = unpk(acc[r][2]);
        float2 go = unpk(acc[r][3]);
        gi.x += bi0; gi.y += bi1;
        gf.x += bf0; gf.y += bf1;
        gg.x += bg0; gg.y += bg1;
        go.x += bo0; go.y += bo1;

        float cp0 = 0.f, cp1 = 0.f;
        if (!first) {
            float2 cp = *(const float2*)(Cin + ((size_t)(gm >> 1)) * D_ + c0);
            cp0 = cp.x; cp1 = cp.y;
        }
        float cn0 = sigf(gf.x) * cp0 + sigf(gi.x) * tanhf_(gg.x);
        float cn1 = sigf(gf.y) * cp1 + sigf(gi.y) * tanhf_(gg.y);
        float hn0 = sigf(go.x) * tanhf_(cn0);
        float hn1 = sigf(go.y) * tanhf_(cn1);

        *(float2*)(Cout + (size_t)gm * D_ + c0) = make_float2(cn0, cn1);
        *(float2*)(Hout + (size_t)gm * D_ + c0) = make_float2(hn0, hn1);
    }
}

// ---------------------------------------------------------------------------
// Gather: out[b,t,:] = active ? H_level8[t*256 + leaf, :] : 0
// ---------------------------------------------------------------------------
__global__ void gather_kernel(float4* __restrict__ out) {
    int idx = blockIdx.x * blockDim.x + threadIdx.x;
    if (idx >= BT_ * D_ / 4) return;
    int bt = idx >> 5;          // D/4 = 32 float4 per row
    int d4 = idx & 31;
    int t  = bt % T_;
    int lf = g_leaf[bt];
    float4 v = make_float4(0.f, 0.f, 0.f, 0.f);
    if (lf >= 0)
        v = ((const float4*)&g_H[0][((size_t)(t * 256 + lf)) * D_])[d4];
    out[idx] = v;
}

// ---------------------------------------------------------------------------
// Launch
// ---------------------------------------------------------------------------
extern "C" void kernel_launch(void* const* d_in, const int* in_sizes, int n_in,
                              void* d_out, int out_size) {
    const float* cross = (const float*)d_in[0];
    const float* emb   = (const float*)d_in[1];
    const float* w_ih  = (const float*)d_in[2];
    const float* w_hh  = (const float*)d_in[3];
    const float* b_ih  = (const float*)d_in[4];
    const float* b_hh  = (const float*)d_in[5];
    // d_in[6] = paths: fixed heap layout, reconstructed analytically.
    float* out = (float*)d_out;

    const int BIG_SMEM   = (256 * 68 + 16 * 512) * 4;   // 102400 B
    const int SMALL_SMEM = (256 * 12 + 16 * 512) * 4;   //  45056 B

    // Sticky attribute; set every call (first, uncaptured call is what matters).
    cudaFuncSetAttribute((const void*)lstm_level_kernel<64, 512, 68>,
                         cudaFuncAttributeMaxDynamicSharedMemorySize, BIG_SMEM);

    prep_kernel<<<512, 256>>>(w_ih, w_hh, b_ih, b_hh);
    leaf_kernel<<<BT_ * 32 / 256, 256>>>(cross);

    for (int k = 0; k <= 8; k++) {
        int M     = T_ << k;
        int dst   = k & 1;
        int first = (k == 0) ? 1 : 0;
        if (k >= 6)
            lstm_level_kernel<64, 512, 68><<<M / 64, 512, BIG_SMEM>>>(k, M, first, dst, emb);
        else
            lstm_level_kernel<8, 256, 12><<<(M + 7) / 8, 256, SMALL_SMEM>>>(k, M, first, dst, emb);
    }

    gather_kernel<<<BT_ * D_ / 4 / 256, 256>>>((float4*)out);
}